// round 15
// baseline (speedup 1.0000x reference)
#include <cuda_runtime.h>
#include <cuda_fp16.h>
#include <cstdint>

#define Bq 16
#define Tq 2048
#define Dq 256
#define Nq 512

#define Q_ELEMS (Bq*Tq*Dq)          /* 8388608 */
#define DIFF_OFF Q_ELEMS
#define IND_OFF  (Q_ELEMS + 1)
#define SEL_BLOCKS (Bq*Tq/8)        /* 4096 */
#define NTOK (Bq*Tq)                /* 32768 */
#define EPS_SEL 0.15f
#define CAND_K 32
#define ASTRIDE 144                  /* smem row stride bytes (128 data + 16 pad) */

// ---------------- scratch (no allocations allowed) ----------------
__device__ float g_cb[Bq*Nq*Dq];                       // e codebook [b][n][d]
__device__ float g_see[Bq*Nq];                         // sum(e^2), XLA-tree order
__device__ float g_sxx[Bq*Tq];                         // sum(x^2), XLA-tree order
__device__ __align__(16) __half g_xh[Bq*Tq*Dq];        // x fp16
__device__ __align__(16) __half g_eh[Bq*Nq*Dq];        // e fp16
__device__ __align__(16) float g_tileMin[NTOK*4];      // per-token per-ntile min
__device__ int g_candCnt[NTOK];
__device__ unsigned long long g_cand[(size_t)NTOK*CAND_K];  // (distbits<<32)|n
__device__ double g_diff_partial[SEL_BLOCKS];

// ---------------- helpers ----------------
__device__ __forceinline__ unsigned long long make_key(float s, int n) {
    unsigned u = __float_as_uint(s);
    u = (u & 0x80000000u) ? ~u : (u | 0x80000000u);
    return ((unsigned long long)u << 32) | (unsigned long long)(0xFFFFFFFFu - (unsigned)n);
}
__device__ __forceinline__ unsigned long long fma2(unsigned long long a,
                                                   unsigned long long x,
                                                   unsigned long long e) {
    asm("fma.rn.f32x2 %0, %1, %2, %0;" : "+l"(a) : "l"(x), "l"(e));
    return a;
}
__device__ __forceinline__ unsigned long long dup2(float v) {
    unsigned long long r; asm("mov.b64 %0, {%1, %1};" : "=l"(r) : "f"(v)); return r;
}
__device__ __forceinline__ unsigned long long pack2(float lo, float hi) {
    unsigned long long r; asm("mov.b64 %0, {%1, %2};" : "=l"(r) : "f"(lo), "f"(hi)); return r;
}
__device__ __forceinline__ void unpack2(unsigned long long v, float& lo, float& hi) {
    asm("mov.b64 {%0, %1}, %2;" : "=f"(lo), "=f"(hi) : "l"(v));
}
__device__ __forceinline__ float warp_tree_sum(float p) {
#pragma unroll
    for (int off = 16; off > 0; off >>= 1)
        p = __fadd_rn(p, __shfl_down_sync(0xffffffffu, p, off));
    return p;
}
__device__ __forceinline__ uint32_t smem_u32(const void* p) {
    uint32_t a;
    asm("{ .reg .u64 t; cvta.to.shared.u64 t, %1; cvt.u32.u64 %0, t; }" : "=r"(a) : "l"(p));
    return a;
}
__device__ __forceinline__ void ldsm_x4(uint32_t r[4], uint32_t addr) {
    asm volatile("ldmatrix.sync.aligned.m8n8.x4.shared.b16 {%0,%1,%2,%3}, [%4];"
        : "=r"(r[0]), "=r"(r[1]), "=r"(r[2]), "=r"(r[3]) : "r"(addr));
}
__device__ __forceinline__ void mma16816(float c[4], const uint32_t a[4],
                                         uint32_t b0, uint32_t b1) {
    asm volatile("mma.sync.aligned.m16n8k16.row.col.f32.f16.f16.f32 "
        "{%0,%1,%2,%3}, {%4,%5,%6,%7}, {%8,%9}, {%0,%1,%2,%3};"
        : "+f"(c[0]), "+f"(c[1]), "+f"(c[2]), "+f"(c[3])
        : "r"(a[0]), "r"(a[1]), "r"(a[2]), "r"(a[3]), "r"(b0), "r"(b1));
}
// exact ref-chain rescore: sequential fp32 fmaf, k ascending
__device__ __forceinline__ float exact_dist(const float* __restrict__ sxr,
                                            const float* __restrict__ er,
                                            float sxx, float see) {
    float acc = 0.f;
    for (int k = 0; k < 256; k += 4) {
        float4 ev = *(const float4*)(er + k);
        acc = __fmaf_rn(sxr[k+0], ev.x, acc);
        acc = __fmaf_rn(sxr[k+1], ev.y, acc);
        acc = __fmaf_rn(sxr[k+2], ev.z, acc);
        acc = __fmaf_rn(sxr[k+3], ev.w, acc);
    }
    return __fadd_rn(__fsub_rn(sxx, __fmul_rn(2.0f, acc)), see);
}

// ---------------- kernel 0: sxx (XLA order) + x fp16 + cand reset ---------
__global__ __launch_bounds__(256) void k_prep(const float* __restrict__ x) {
    int tid = threadIdx.x, lane = tid & 31, wid = tid >> 5;
    int gidx = blockIdx.x * 256 + tid;
    if (gidx < NTOK) g_candCnt[gidx] = 0;
    int token = blockIdx.x * 8 + wid;
    const float* xt = x + (size_t)token * Dq;
    float p = 0.f;
#pragma unroll
    for (int j = 0; j < 8; j++) {
        float c = xt[lane + 32*j];
        p = __fadd_rn(p, __fmul_rn(c, c));
        g_xh[(size_t)token * Dq + lane + 32*j] = __float2half_rn(c);
    }
    p = warp_tree_sum(p);
    if (lane == 0) g_sxx[token] = p;
}

// ---------------- kernel 1: codebook build, double-buffered -------
#define CBS 17
__global__ __launch_bounds__(128) void k_codebook(const float* __restrict__ emb,
                                                  const float* __restrict__ spk) {
    __shared__ float As[2][256*CBS];
    __shared__ unsigned long long Ms2[2][128];
    __shared__ float normS[16];

    int tid = threadIdx.x;
    int lane = tid & 31, wid = tid >> 5;
    int n = blockIdx.x;
    const float* embn = emb + (size_t)n * (Dq*Dq);
    const float* mul  = spk + 2*Bq*Dq;
    const float* addv = spk + 1*Bq*Dq;

    unsigned long long accp[2][8];
#pragma unroll
    for (int r = 0; r < 2; r++)
#pragma unroll
        for (int p = 0; p < 8; p++) accp[r][p] = 0ull;

    int mp = tid >> 4, mj = tid & 15;
    float4 pa[8];
    unsigned long long mpre;
    {
#pragma unroll
        for (int i = 0; i < 8; i++) {
            int idx = tid + i*128;
            int d = idx >> 2, jg = idx & 3;
            pa[i] = *(const float4*)(embn + (size_t)d*256 + jg*4);
        }
        mpre = pack2(mul[(2*mp)*256 + mj], mul[(2*mp+1)*256 + mj]);
    }

    for (int c = 0; c < 16; c++) {
        int buf = c & 1;
        __syncthreads();
#pragma unroll
        for (int i = 0; i < 8; i++) {
            int idx = tid + i*128;
            int d = idx >> 2, jg = idx & 3;
            int base = d*CBS + jg*4;
            As[buf][base+0] = pa[i].x; As[buf][base+1] = pa[i].y;
            As[buf][base+2] = pa[i].z; As[buf][base+3] = pa[i].w;
        }
        Ms2[buf][tid] = mpre;
        __syncthreads();
        if (c < 15) {
            int kc = (c + 1) * 16;
#pragma unroll
            for (int i = 0; i < 8; i++) {
                int idx = tid + i*128;
                int d = idx >> 2, jg = idx & 3;
                pa[i] = *(const float4*)(embn + (size_t)d*256 + kc + jg*4);
            }
            mpre = pack2(mul[(2*mp)*256 + kc + mj], mul[(2*mp+1)*256 + kc + mj]);
        }
        const float* a0 = As[buf] + tid*CBS;
        const float* a1 = As[buf] + (tid+128)*CBS;
#pragma unroll
        for (int j = 0; j < 16; j++) {
            unsigned long long xv0 = dup2(a0[j]);
            unsigned long long xv1 = dup2(a1[j]);
#pragma unroll
            for (int p = 0; p < 8; p++) {
                unsigned long long m = Ms2[buf][p*16 + j];
                accp[0][p] = fma2(accp[0][p], xv0, m);
                accp[1][p] = fma2(accp[1][p], xv1, m);
            }
        }
    }

    float acc[2][16];
#pragma unroll
    for (int r = 0; r < 2; r++)
#pragma unroll
        for (int p = 0; p < 8; p++)
            unpack2(accp[r][p], acc[r][2*p], acc[r][2*p+1]);

    float* Ep = (float*)As;
    __syncthreads();
#pragma unroll
    for (int r = 0; r < 2; r++)
#pragma unroll
        for (int b = 0; b < 16; b++) Ep[b*258 + tid + r*128] = acc[r][b];
    __syncthreads();

#pragma unroll
    for (int bb = 0; bb < 4; bb++) {
        int b = wid*4 + bb;
        const float* row = Ep + b*258;
        float p = 0.f;
#pragma unroll
        for (int j = 0; j < 8; j++) {
            float c = row[lane + 32*j];
            p = __fadd_rn(p, __fmul_rn(c, c));
        }
        p = warp_tree_sum(p);
        if (lane == 0) normS[b] = __fsqrt_rn(p);
    }
    __syncthreads();

#pragma unroll
    for (int r = 0; r < 2; r++) {
        int d = tid + r*128;
#pragma unroll
        for (int b = 0; b < 16; b++) {
            float ef = __fadd_rn(__fdiv_rn(acc[r][b], normS[b]), addv[b*256 + d]);
            size_t o = ((size_t)(b*Nq + n))*Dq + d;
            g_cb[o] = ef;
            Ep[b*258 + d] = ef;
            g_eh[o] = __float2half_rn(ef);
        }
    }
    __syncthreads();

#pragma unroll
    for (int bb = 0; bb < 4; bb++) {
        int b = wid*4 + bb;
        const float* row = Ep + b*258;
        float p = 0.f;
#pragma unroll
        for (int j = 0; j < 8; j++) {
            float c = row[lane + 32*j];
            p = __fadd_rn(p, __fmul_rn(c, c));
        }
        p = warp_tree_sum(p);
        if (lane == 0) g_see[b*Nq + n] = p;
    }
}

// ---------------- kernel 2: HMMA fp16 dist GEMM + candidate emit ----------
// tile 128t x 128n; NO dist matrix: per-token tile-min + eps-window
// candidates appended to g_cand (set deterministic; order irrelevant).
__global__ __launch_bounds__(256, 2) void k_scores_mma() {
    __shared__ __align__(16) unsigned char sA[128*ASTRIDE];
    __shared__ __align__(16) unsigned char sB[128*ASTRIDE];
    __shared__ float sMinW[4][128];
    __shared__ float sMin[128];

    int tid = threadIdx.x, wid = tid >> 5, lane = tid & 31;
    int tile = blockIdx.x;
    int b = tile >> 6, rem = tile & 63;
    int t0 = (rem >> 2) * 128, n0 = (rem & 3) * 128;
    int wy = wid >> 2, wx = wid & 3;

    float acc[4][4][4];
#pragma unroll
    for (int i = 0; i < 4; i++)
#pragma unroll
        for (int j = 0; j < 4; j++)
#pragma unroll
            for (int c = 0; c < 4; c++) acc[i][j][c] = 0.f;

    int lrow = tid >> 1, lhalf = tid & 1;

    uint32_t aBase = smem_u32(sA), bBase = smem_u32(sB);
    uint32_t aAddr0 = aBase + (uint32_t)(wy*64 + (lane & 15)) * ASTRIDE + ((lane >> 4) * 16);
    uint32_t bAddr0 = bBase + (uint32_t)(wx*32 + ((lane >> 4) << 3) + (lane & 7)) * ASTRIDE
                            + (((lane >> 3) & 1) * 16);

    const __half* gX = g_xh + ((size_t)(b*Tq + t0)) * Dq;
    const __half* gE = g_eh + ((size_t)(b*Nq + n0)) * Dq;

    uint4 pa[4], pb[4];
    {
        const uint4* srcA = (const uint4*)(gX + (size_t)lrow*Dq + lhalf*32);
        const uint4* srcB = (const uint4*)(gE + (size_t)lrow*Dq + lhalf*32);
#pragma unroll
        for (int q = 0; q < 4; q++) { pa[q] = srcA[q]; pb[q] = srcB[q]; }
    }

    for (int c = 0; c < 4; c++) {
        __syncthreads();
        {
            uint4* dstA = (uint4*)(sA + lrow*ASTRIDE + lhalf*64);
            uint4* dstB = (uint4*)(sB + lrow*ASTRIDE + lhalf*64);
#pragma unroll
            for (int q = 0; q < 4; q++) { dstA[q] = pa[q]; dstB[q] = pb[q]; }
        }
        __syncthreads();
        if (c < 3) {
            int kc = (c + 1) * 64;
            const uint4* srcA = (const uint4*)(gX + (size_t)lrow*Dq + kc + lhalf*32);
            const uint4* srcB = (const uint4*)(gE + (size_t)lrow*Dq + kc + lhalf*32);
#pragma unroll
            for (int q = 0; q < 4; q++) { pa[q] = srcA[q]; pb[q] = srcB[q]; }
        }
#pragma unroll
        for (int s = 0; s < 4; s++) {
            uint32_t bfr[2][4];
#pragma unroll
            for (int p = 0; p < 2; p++)
                ldsm_x4(bfr[p], bAddr0 + (uint32_t)(p*16)*ASTRIDE + s*32);
#pragma unroll
            for (int mt = 0; mt < 4; mt++) {
                uint32_t afr[4];
                ldsm_x4(afr, aAddr0 + (uint32_t)(mt*16)*ASTRIDE + s*32);
#pragma unroll
                for (int nt = 0; nt < 4; nt++) {
                    int p = nt >> 1, q = nt & 1;
                    mma16816(acc[mt][nt], afr, bfr[p][2*q], bfr[p][2*q + 1]);
                }
            }
        }
    }

    // epilogue: dists in regs, tile-local per-token min, candidate emit
    int gid = lane >> 2, tid4 = lane & 3;
    float dstA[4][8], dstB[4][8];
#pragma unroll
    for (int mt = 0; mt < 4; mt++) {
        int t = t0 + wy*64 + mt*16 + gid;
        float sx0 = g_sxx[b*Tq + t], sx1 = g_sxx[b*Tq + t + 8];
        float mnA = 3.4e38f, mnB = 3.4e38f;
#pragma unroll
        for (int nt = 0; nt < 4; nt++) {
            int n = n0 + wx*32 + nt*8 + tid4*2;
            float2 se = *(const float2*)(g_see + b*Nq + n);
            float a0 = (sx0 - 2.0f*acc[mt][nt][0]) + se.x;
            float a1 = (sx0 - 2.0f*acc[mt][nt][1]) + se.y;
            float b0 = (sx1 - 2.0f*acc[mt][nt][2]) + se.x;
            float b1 = (sx1 - 2.0f*acc[mt][nt][3]) + se.y;
            dstA[mt][2*nt] = a0; dstA[mt][2*nt+1] = a1;
            dstB[mt][2*nt] = b0; dstB[mt][2*nt+1] = b1;
            mnA = fminf(mnA, fminf(a0, a1));
            mnB = fminf(mnB, fminf(b0, b1));
        }
        mnA = fminf(mnA, __shfl_xor_sync(0xffffffffu, mnA, 1));
        mnA = fminf(mnA, __shfl_xor_sync(0xffffffffu, mnA, 2));
        mnB = fminf(mnB, __shfl_xor_sync(0xffffffffu, mnB, 1));
        mnB = fminf(mnB, __shfl_xor_sync(0xffffffffu, mnB, 2));
        if (tid4 == 0) {
            sMinW[wx][wy*64 + mt*16 + gid] = mnA;
            sMinW[wx][wy*64 + mt*16 + 8 + gid] = mnB;
        }
    }
    __syncthreads();
    if (tid < 128) {
        float m = fminf(fminf(sMinW[0][tid], sMinW[1][tid]),
                        fminf(sMinW[2][tid], sMinW[3][tid]));
        sMin[tid] = m;
        g_tileMin[((size_t)(b*Tq + t0 + tid))*4 + (n0 >> 7)] = m;
    }
    __syncthreads();

#pragma unroll
    for (int mt = 0; mt < 4; mt++) {
        int tlA = wy*64 + mt*16 + gid, tlB = tlA + 8;
        float thrA = sMin[tlA] + EPS_SEL, thrB = sMin[tlB] + EPS_SEL;
        int tokA = b*Tq + t0 + tlA, tokB = b*Tq + t0 + tlB;
#pragma unroll
        for (int j = 0; j < 8; j++) {
            int n = n0 + wx*32 + (j >> 1)*8 + tid4*2 + (j & 1);
            float da = dstA[mt][j];
            if (da <= thrA) {
                int idx = atomicAdd(&g_candCnt[tokA], 1);
                if (idx < CAND_K)
                    g_cand[(size_t)tokA*CAND_K + idx] =
                        ((unsigned long long)__float_as_uint(da) << 32) | (unsigned)n;
            }
            float db = dstB[mt][j];
            if (db <= thrB) {
                int idx = atomicAdd(&g_candCnt[tokB], 1);
                if (idx < CAND_K)
                    g_cand[(size_t)tokB*CAND_K + idx] =
                        ((unsigned long long)__float_as_uint(db) << 32) | (unsigned)n;
            }
        }
    }
}

// ---------------- kernel 3: select (candidate-based) + gather fused --------
__global__ __launch_bounds__(256) void k_select(const float* __restrict__ x,
                                                float* __restrict__ out) {
    __shared__ float sx[8][256];
    __shared__ double s_red[8];

    int tid = threadIdx.x, lane = tid & 31, wid = tid >> 5;
    int token = blockIdx.x * 8 + wid;
    int b = token >> 11;

    float4 tm = *(const float4*)(g_tileMin + (size_t)token * 4);
    float dmin = fminf(fminf(tm.x, tm.y), fminf(tm.z, tm.w));
    float thr = dmin + EPS_SEL;
    int cnt = g_candCnt[token];

    unsigned nstar;
    if (cnt <= CAND_K) {
        float d = 3.4e38f; int n = 0;
        if (lane < cnt) {
            unsigned long long pr = g_cand[(size_t)token*CAND_K + lane];
            d = __uint_as_float((unsigned)(pr >> 32));
            n = (int)(unsigned)pr;
        }
        bool cand = (lane < cnt) && (d <= thr);
        unsigned bal = __ballot_sync(0xffffffffu, cand);
        if (__popc(bal) == 1) {
            int src = __ffs(bal) - 1;
            nstar = __shfl_sync(0xffffffffu, (unsigned)n, src);
        } else {
            float sxx = g_sxx[token];
            const float* xr = x + (size_t)token * Dq;
#pragma unroll
            for (int j = 0; j < 8; j++) sx[wid][lane + 32*j] = xr[lane + 32*j];
            __syncwarp();
            unsigned long long key = 0ull;
            if (cand) {
                float dist = exact_dist(sx[wid], g_cb + ((size_t)(b*Nq + n))*Dq,
                                        sxx, g_see[b*Nq + n]);
                key = make_key(-dist, n);
            }
#pragma unroll
            for (int off = 16; off > 0; off >>= 1) {
                unsigned long long o = __shfl_xor_sync(0xffffffffu, key, off);
                if (o > key) key = o;
            }
            nstar = 0xFFFFFFFFu - (unsigned)key;
        }
    } else {
        // overflow fallback: deterministic full exact rescore over all 512 n
        float sxx = g_sxx[token];
        const float* xr = x + (size_t)token * Dq;
#pragma unroll
        for (int j = 0; j < 8; j++) sx[wid][lane + 32*j] = xr[lane + 32*j];
        __syncwarp();
        unsigned long long bk = 0ull;
        for (int base = 0; base < Nq; base += 32) {
            int n = base + lane;
            float dist = exact_dist(sx[wid], g_cb + ((size_t)(b*Nq + n))*Dq,
                                    sxx, g_see[b*Nq + n]);
            unsigned long long key = make_key(-dist, n);
            if (key > bk) bk = key;
        }
#pragma unroll
        for (int off = 16; off > 0; off >>= 1) {
            unsigned long long o = __shfl_xor_sync(0xffffffffu, bk, off);
            if (o > bk) bk = o;
        }
        nstar = 0xFFFFFFFFu - (unsigned)bk;
    }
    if (lane == 0) out[IND_OFF + token] = (float)nstar;

    // ---- fused gather + quantize + diff ----
    const float4* q4 = (const float4*)(g_cb + ((size_t)(b*Nq) + nstar) * Dq);
    const float4* x4 = (const float4*)(x + (size_t)token * Dq);
    float4* o4 = (float4*)(out + (size_t)token * Dq);

    float s32 = 0.f;
    double s = 0.0;
#pragma unroll
    for (int p = 0; p < 2; p++) {
        int f = lane + p*32;
        float4 q = q4[f], xv = x4[f];
        float dx = __fsub_rn(q.x, xv.x), dy = __fsub_rn(q.y, xv.y);
        float dz = __fsub_rn(q.z, xv.z), dw = __fsub_rn(q.w, xv.w);
        float4 r;
        r.x = __fmul_rn(__fadd_rn(q.x, __fadd_rn(xv.x, dx)), 0.5f);
        r.y = __fmul_rn(__fadd_rn(q.y, __fadd_rn(xv.y, dy)), 0.5f);
        r.z = __fmul_rn(__fadd_rn(q.z, __fadd_rn(xv.z, dz)), 0.5f);
        r.w = __fmul_rn(__fadd_rn(q.w, __fadd_rn(xv.w, dw)), 0.5f);
        o4[f] = r;
        s32 = fmaf(dx, dx, s32); s32 = fmaf(dy, dy, s32);
        s32 = fmaf(dz, dz, s32); s32 = fmaf(dw, dw, s32);
        if (p == 0) { s += (double)s32; s32 = 0.f; }
    }
    s += (double)s32;

#pragma unroll
    for (int off = 16; off > 0; off >>= 1) s += __shfl_down_sync(0xffffffffu, s, off);
    if (lane == 0) s_red[wid] = s;
    __syncthreads();
    if (tid == 0) {
        double t = 0.0;
        for (int i = 0; i < 8; i++) t += s_red[i];
        g_diff_partial[blockIdx.x] = t;
    }
}

// ---------------- kernel 4: deterministic final diff reduce ---------------
__global__ __launch_bounds__(256) void k_diff(float* __restrict__ out) {
    __shared__ double sr[256];
    int tid = threadIdx.x;
    double s = 0.0;
    for (int i = tid; i < SEL_BLOCKS; i += 256) s += g_diff_partial[i];
    sr[tid] = s;
    __syncthreads();
    for (int off = 128; off > 0; off >>= 1) {
        if (tid < off) sr[tid] += sr[tid + off];
        __syncthreads();
    }
    if (tid == 0) out[DIFF_OFF] = (float)(sr[0] / (double)Q_ELEMS);
}

// ---------------- launch ----------------
extern "C" void kernel_launch(void* const* d_in, const int* in_sizes, int n_in,
                              void* d_out, int out_size) {
    const float* inp = (const float*)d_in[0];   // (16,2048,256)
    const float* spk = (const float*)d_in[1];   // (3,16,256)
    const float* emb = (const float*)d_in[2];   // (512,256,256)
    float* out = (float*)d_out;                 // [quantize | diff | embed_ind]

    k_prep<<<Bq*Tq/8, 256>>>(inp);
    k_codebook<<<512, 128>>>(emb, spk);
    k_scores_mma<<<1024, 256>>>();
    k_select<<<SEL_BLOCKS, 256>>>(inp, out);
    k_diff<<<1, 256>>>(out);
}

// round 16
// speedup vs baseline: 1.1422x; 1.1422x over previous
#include <cuda_runtime.h>
#include <cuda_fp16.h>
#include <cstdint>

#define Bq 16
#define Tq 2048
#define Dq 256
#define Nq 512

#define Q_ELEMS (Bq*Tq*Dq)          /* 8388608 */
#define DIFF_OFF Q_ELEMS
#define IND_OFF  (Q_ELEMS + 1)
#define SEL_BLOCKS (Bq*Tq/8)        /* 4096 */
#define NTOK (Bq*Tq)                /* 32768 */
#define EPS_SEL 0.15f
#define CAND_MAX 64
#define ASTRIDE 144                  /* smem row stride bytes (128 data + 16 pad) */

// ---------------- scratch (no allocations allowed) ----------------
__device__ float g_cb[Bq*Nq*Dq];                       // e codebook [b][n][d]
__device__ float g_see[Bq*Nq];                         // sum(e^2), XLA-tree order
__device__ float g_sxx[Bq*Tq];                         // sum(x^2), XLA-tree order
__device__ __align__(16) __half g_xh[Bq*Tq*Dq];        // x fp16
__device__ __align__(16) __half g_eh[Bq*Nq*Dq];        // e fp16
__device__ float g_dot[(size_t)Bq*Tq*Nq];              // approx DISTS, 67 MB
__device__ __align__(16) float g_tileMin[NTOK*4];      // per-token per-ntile min
__device__ double g_diff_partial[SEL_BLOCKS];

// ---------------- helpers ----------------
__device__ __forceinline__ unsigned long long make_key(float s, int n) {
    unsigned u = __float_as_uint(s);
    u = (u & 0x80000000u) ? ~u : (u | 0x80000000u);
    return ((unsigned long long)u << 32) | (unsigned long long)(0xFFFFFFFFu - (unsigned)n);
}
__device__ __forceinline__ unsigned long long fma2(unsigned long long a,
                                                   unsigned long long x,
                                                   unsigned long long e) {
    asm("fma.rn.f32x2 %0, %1, %2, %0;" : "+l"(a) : "l"(x), "l"(e));
    return a;
}
__device__ __forceinline__ unsigned long long dup2(float v) {
    unsigned long long r; asm("mov.b64 %0, {%1, %1};" : "=l"(r) : "f"(v)); return r;
}
__device__ __forceinline__ unsigned long long pack2(float lo, float hi) {
    unsigned long long r; asm("mov.b64 %0, {%1, %2};" : "=l"(r) : "f"(lo), "f"(hi)); return r;
}
__device__ __forceinline__ void unpack2(unsigned long long v, float& lo, float& hi) {
    asm("mov.b64 {%0, %1}, %2;" : "=f"(lo), "=f"(hi) : "l"(v));
}
__device__ __forceinline__ float warp_tree_sum(float p) {
#pragma unroll
    for (int off = 16; off > 0; off >>= 1)
        p = __fadd_rn(p, __shfl_down_sync(0xffffffffu, p, off));
    return p;
}
__device__ __forceinline__ uint32_t smem_u32(const void* p) {
    uint32_t a;
    asm("{ .reg .u64 t; cvta.to.shared.u64 t, %1; cvt.u32.u64 %0, t; }" : "=r"(a) : "l"(p));
    return a;
}
__device__ __forceinline__ void ldsm_x4(uint32_t r[4], uint32_t addr) {
    asm volatile("ldmatrix.sync.aligned.m8n8.x4.shared.b16 {%0,%1,%2,%3}, [%4];"
        : "=r"(r[0]), "=r"(r[1]), "=r"(r[2]), "=r"(r[3]) : "r"(addr));
}
__device__ __forceinline__ void mma16816(float c[4], const uint32_t a[4],
                                         uint32_t b0, uint32_t b1) {
    asm volatile("mma.sync.aligned.m16n8k16.row.col.f32.f16.f16.f32 "
        "{%0,%1,%2,%3}, {%4,%5,%6,%7}, {%8,%9}, {%0,%1,%2,%3};"
        : "+f"(c[0]), "+f"(c[1]), "+f"(c[2]), "+f"(c[3])
        : "r"(a[0]), "r"(a[1]), "r"(a[2]), "r"(a[3]), "r"(b0), "r"(b1));
}
// exact ref-chain rescore: sequential fp32 fmaf, k ascending
__device__ __forceinline__ float exact_dist(const float* __restrict__ sxr,
                                            const float* __restrict__ er,
                                            float sxx, float see) {
    float acc = 0.f;
    for (int k = 0; k < 256; k += 4) {
        float4 ev = *(const float4*)(er + k);
        acc = __fmaf_rn(sxr[k+0], ev.x, acc);
        acc = __fmaf_rn(sxr[k+1], ev.y, acc);
        acc = __fmaf_rn(sxr[k+2], ev.z, acc);
        acc = __fmaf_rn(sxr[k+3], ev.w, acc);
    }
    return __fadd_rn(__fsub_rn(sxx, __fmul_rn(2.0f, acc)), see);
}

// ---------------- kernel 0: sxx (XLA order) + x fp16 --------------
__global__ __launch_bounds__(256) void k_prep(const float* __restrict__ x) {
    int tid = threadIdx.x, lane = tid & 31, wid = tid >> 5;
    int token = blockIdx.x * 8 + wid;
    const float* xt = x + (size_t)token * Dq;
    float p = 0.f;
#pragma unroll
    for (int j = 0; j < 8; j++) {
        float c = xt[lane + 32*j];
        p = __fadd_rn(p, __fmul_rn(c, c));
        g_xh[(size_t)token * Dq + lane + 32*j] = __float2half_rn(c);
    }
    p = warp_tree_sum(p);
    if (lane == 0) g_sxx[token] = p;
}

// ---------------- kernel 1: codebook build, double-buffered -------
#define CBS 17
__global__ __launch_bounds__(128) void k_codebook(const float* __restrict__ emb,
                                                  const float* __restrict__ spk) {
    __shared__ float As[2][256*CBS];
    __shared__ unsigned long long Ms2[2][128];
    __shared__ float normS[16];

    int tid = threadIdx.x;
    int lane = tid & 31, wid = tid >> 5;
    int n = blockIdx.x;
    const float* embn = emb + (size_t)n * (Dq*Dq);
    const float* mul  = spk + 2*Bq*Dq;
    const float* addv = spk + 1*Bq*Dq;

    unsigned long long accp[2][8];
#pragma unroll
    for (int r = 0; r < 2; r++)
#pragma unroll
        for (int p = 0; p < 8; p++) accp[r][p] = 0ull;

    int mp = tid >> 4, mj = tid & 15;
    float4 pa[8];
    unsigned long long mpre;
    {
#pragma unroll
        for (int i = 0; i < 8; i++) {
            int idx = tid + i*128;
            int d = idx >> 2, jg = idx & 3;
            pa[i] = *(const float4*)(embn + (size_t)d*256 + jg*4);
        }
        mpre = pack2(mul[(2*mp)*256 + mj], mul[(2*mp+1)*256 + mj]);
    }

    for (int c = 0; c < 16; c++) {
        int buf = c & 1;
        __syncthreads();
#pragma unroll
        for (int i = 0; i < 8; i++) {
            int idx = tid + i*128;
            int d = idx >> 2, jg = idx & 3;
            int base = d*CBS + jg*4;
            As[buf][base+0] = pa[i].x; As[buf][base+1] = pa[i].y;
            As[buf][base+2] = pa[i].z; As[buf][base+3] = pa[i].w;
        }
        Ms2[buf][tid] = mpre;
        __syncthreads();
        if (c < 15) {
            int kc = (c + 1) * 16;
#pragma unroll
            for (int i = 0; i < 8; i++) {
                int idx = tid + i*128;
                int d = idx >> 2, jg = idx & 3;
                pa[i] = *(const float4*)(embn + (size_t)d*256 + kc + jg*4);
            }
            mpre = pack2(mul[(2*mp)*256 + kc + mj], mul[(2*mp+1)*256 + kc + mj]);
        }
        const float* a0 = As[buf] + tid*CBS;
        const float* a1 = As[buf] + (tid+128)*CBS;
#pragma unroll
        for (int j = 0; j < 16; j++) {
            unsigned long long xv0 = dup2(a0[j]);
            unsigned long long xv1 = dup2(a1[j]);
#pragma unroll
            for (int p = 0; p < 8; p++) {
                unsigned long long m = Ms2[buf][p*16 + j];
                accp[0][p] = fma2(accp[0][p], xv0, m);
                accp[1][p] = fma2(accp[1][p], xv1, m);
            }
        }
    }

    float acc[2][16];
#pragma unroll
    for (int r = 0; r < 2; r++)
#pragma unroll
        for (int p = 0; p < 8; p++)
            unpack2(accp[r][p], acc[r][2*p], acc[r][2*p+1]);

    float* Ep = (float*)As;
    __syncthreads();
#pragma unroll
    for (int r = 0; r < 2; r++)
#pragma unroll
        for (int b = 0; b < 16; b++) Ep[b*258 + tid + r*128] = acc[r][b];
    __syncthreads();

#pragma unroll
    for (int bb = 0; bb < 4; bb++) {
        int b = wid*4 + bb;
        const float* row = Ep + b*258;
        float p = 0.f;
#pragma unroll
        for (int j = 0; j < 8; j++) {
            float c = row[lane + 32*j];
            p = __fadd_rn(p, __fmul_rn(c, c));
        }
        p = warp_tree_sum(p);
        if (lane == 0) normS[b] = __fsqrt_rn(p);
    }
    __syncthreads();

#pragma unroll
    for (int r = 0; r < 2; r++) {
        int d = tid + r*128;
#pragma unroll
        for (int b = 0; b < 16; b++) {
            float ef = __fadd_rn(__fdiv_rn(acc[r][b], normS[b]), addv[b*256 + d]);
            size_t o = ((size_t)(b*Nq + n))*Dq + d;
            g_cb[o] = ef;
            Ep[b*258 + d] = ef;
            g_eh[o] = __float2half_rn(ef);
        }
    }
    __syncthreads();

#pragma unroll
    for (int bb = 0; bb < 4; bb++) {
        int b = wid*4 + bb;
        const float* row = Ep + b*258;
        float p = 0.f;
#pragma unroll
        for (int j = 0; j < 8; j++) {
            float c = row[lane + 32*j];
            p = __fadd_rn(p, __fmul_rn(c, c));
        }
        p = warp_tree_sum(p);
        if (lane == 0) g_see[b*Nq + n] = p;
    }
}

// ---------------- kernel 2: HMMA fp16 dist GEMM + fused tile-min ----------
// tile 128t x 128n; writes dist matrix AND per-token tile min (no extra regs).
__global__ __launch_bounds__(256, 2) void k_scores_mma() {
    __shared__ __align__(16) unsigned char sA[128*ASTRIDE];
    __shared__ __align__(16) unsigned char sB[128*ASTRIDE];
    __shared__ float sMinW[4][128];

    int tid = threadIdx.x, wid = tid >> 5, lane = tid & 31;
    int tile = blockIdx.x;
    int b = tile >> 6, rem = tile & 63;
    int t0 = (rem >> 2) * 128, n0 = (rem & 3) * 128;
    int wy = wid >> 2, wx = wid & 3;

    float acc[4][4][4];
#pragma unroll
    for (int i = 0; i < 4; i++)
#pragma unroll
        for (int j = 0; j < 4; j++)
#pragma unroll
            for (int c = 0; c < 4; c++) acc[i][j][c] = 0.f;

    int lrow = tid >> 1, lhalf = tid & 1;

    uint32_t aBase = smem_u32(sA), bBase = smem_u32(sB);
    uint32_t aAddr0 = aBase + (uint32_t)(wy*64 + (lane & 15)) * ASTRIDE + ((lane >> 4) * 16);
    uint32_t bAddr0 = bBase + (uint32_t)(wx*32 + ((lane >> 4) << 3) + (lane & 7)) * ASTRIDE
                            + (((lane >> 3) & 1) * 16);

    const __half* gX = g_xh + ((size_t)(b*Tq + t0)) * Dq;
    const __half* gE = g_eh + ((size_t)(b*Nq + n0)) * Dq;

    uint4 pa[4], pb[4];
    {
        const uint4* srcA = (const uint4*)(gX + (size_t)lrow*Dq + lhalf*32);
        const uint4* srcB = (const uint4*)(gE + (size_t)lrow*Dq + lhalf*32);
#pragma unroll
        for (int q = 0; q < 4; q++) { pa[q] = srcA[q]; pb[q] = srcB[q]; }
    }

    for (int c = 0; c < 4; c++) {
        __syncthreads();
        {
            uint4* dstA = (uint4*)(sA + lrow*ASTRIDE + lhalf*64);
            uint4* dstB = (uint4*)(sB + lrow*ASTRIDE + lhalf*64);
#pragma unroll
            for (int q = 0; q < 4; q++) { dstA[q] = pa[q]; dstB[q] = pb[q]; }
        }
        __syncthreads();
        if (c < 3) {
            int kc = (c + 1) * 64;
            const uint4* srcA = (const uint4*)(gX + (size_t)lrow*Dq + kc + lhalf*32);
            const uint4* srcB = (const uint4*)(gE + (size_t)lrow*Dq + kc + lhalf*32);
#pragma unroll
            for (int q = 0; q < 4; q++) { pa[q] = srcA[q]; pb[q] = srcB[q]; }
        }
#pragma unroll
        for (int s = 0; s < 4; s++) {
            uint32_t bfr[2][4];
#pragma unroll
            for (int p = 0; p < 2; p++)
                ldsm_x4(bfr[p], bAddr0 + (uint32_t)(p*16)*ASTRIDE + s*32);
#pragma unroll
            for (int mt = 0; mt < 4; mt++) {
                uint32_t afr[4];
                ldsm_x4(afr, aAddr0 + (uint32_t)(mt*16)*ASTRIDE + s*32);
#pragma unroll
                for (int nt = 0; nt < 4; nt++) {
                    int p = nt >> 1, q = nt & 1;
                    mma16816(acc[mt][nt], afr, bfr[p][2*q], bfr[p][2*q + 1]);
                }
            }
        }
    }

    // epilogue: store dist, fold min on the fly (no extra register arrays)
    int gid = lane >> 2, tid4 = lane & 3;
#pragma unroll
    for (int mt = 0; mt < 4; mt++) {
        int t = t0 + wy*64 + mt*16 + gid;
        float sx0 = g_sxx[b*Tq + t], sx1 = g_sxx[b*Tq + t + 8];
        float* d0 = g_dot + ((size_t)(b*Tq) + t) * Nq;
        float* d1 = g_dot + ((size_t)(b*Tq) + t + 8) * Nq;
        float mnA = 3.4e38f, mnB = 3.4e38f;
#pragma unroll
        for (int nt = 0; nt < 4; nt++) {
            int n = n0 + wx*32 + nt*8 + tid4*2;
            float2 se = *(const float2*)(g_see + b*Nq + n);
            float a0 = (sx0 - 2.0f*acc[mt][nt][0]) + se.x;
            float a1 = (sx0 - 2.0f*acc[mt][nt][1]) + se.y;
            float b0 = (sx1 - 2.0f*acc[mt][nt][2]) + se.x;
            float b1 = (sx1 - 2.0f*acc[mt][nt][3]) + se.y;
            *(float2*)(d0 + n) = make_float2(a0, a1);
            *(float2*)(d1 + n) = make_float2(b0, b1);
            mnA = fminf(mnA, fminf(a0, a1));
            mnB = fminf(mnB, fminf(b0, b1));
        }
        mnA = fminf(mnA, __shfl_xor_sync(0xffffffffu, mnA, 1));
        mnA = fminf(mnA, __shfl_xor_sync(0xffffffffu, mnA, 2));
        mnB = fminf(mnB, __shfl_xor_sync(0xffffffffu, mnB, 1));
        mnB = fminf(mnB, __shfl_xor_sync(0xffffffffu, mnB, 2));
        if (tid4 == 0) {
            sMinW[wx][wy*64 + mt*16 + gid] = mnA;
            sMinW[wx][wy*64 + mt*16 + 8 + gid] = mnB;
        }
    }
    __syncthreads();
    if (tid < 128) {
        float m = fminf(fminf(sMinW[0][tid], sMinW[1][tid]),
                        fminf(sMinW[2][tid], sMinW[3][tid]));
        g_tileMin[((size_t)(b*Tq + t0 + tid))*4 + (n0 >> 7)] = m;
    }
}

// ---------------- kernel 3: select (tile-pruned scan) + gather fused ------
__global__ __launch_bounds__(256) void k_select(const float* __restrict__ x,
                                                float* __restrict__ out) {
    __shared__ int candN[8][CAND_MAX];
    __shared__ float sx[8][256];
    __shared__ double s_red[8];

    int tid = threadIdx.x, lane = tid & 31, wid = tid >> 5;
    int token = blockIdx.x * 8 + wid;
    int b = token >> 11;

    float4 tmv = *(const float4*)(g_tileMin + (size_t)token * 4);
    float tms[4] = {tmv.x, tmv.y, tmv.z, tmv.w};
    float dmin = fminf(fminf(tmv.x, tmv.y), fminf(tmv.z, tmv.w));
    float thr = dmin + EPS_SEL;
    const float4* dist4 = (const float4*)(g_dot + (size_t)token * Nq);

    int total = 0;
#pragma unroll
    for (int t = 0; t < 4; t++) {
        if (tms[t] <= thr) {   // warp-uniform branch
            float4 dv = dist4[t*32 + lane];
            unsigned m4 = 0;
            if (dv.x <= thr) m4 |= 1u;
            if (dv.y <= thr) m4 |= 2u;
            if (dv.z <= thr) m4 |= 4u;
            if (dv.w <= thr) m4 |= 8u;
            int cntl = __popc(m4);
            int incl = cntl;
#pragma unroll
            for (int off = 1; off < 32; off <<= 1) {
                int o = __shfl_up_sync(0xffffffffu, incl, off);
                if (lane >= off) incl += o;
            }
            int wtot = __shfl_sync(0xffffffffu, incl, 31);
            int base = total + incl - cntl;
            int c = 0;
#pragma unroll
            for (int j = 0; j < 4; j++)
                if (m4 & (1u << j)) {
                    int idx = base + c++;
                    if (idx < CAND_MAX)
                        candN[wid][idx] = t*128 + 4*lane + j;
                }
            total += wtot;
        }
    }
    __syncwarp();

    unsigned nstar;
    if (total == 1) {
        nstar = (unsigned)candN[wid][0];
    } else {
        float sxx = g_sxx[token];
        const float* xr = x + (size_t)token * Dq;
#pragma unroll
        for (int j = 0; j < 8; j++) sx[wid][lane + 32*j] = xr[lane + 32*j];
        __syncwarp();
        unsigned long long bk = 0ull;
        if (total <= CAND_MAX) {
            for (int base = 0; base < total; base += 32) {
                int idx = base + lane;
                unsigned long long key = 0ull;
                if (idx < total) {
                    int n = candN[wid][idx];
                    float dist = exact_dist(sx[wid], g_cb + ((size_t)(b*Nq + n))*Dq,
                                            sxx, g_see[b*Nq + n]);
                    key = make_key(-dist, n);
                }
                if (key > bk) bk = key;
            }
        } else {
            // overflow: deterministic full exact rescore
            for (int base = 0; base < Nq; base += 32) {
                int n = base + lane;
                float dist = exact_dist(sx[wid], g_cb + ((size_t)(b*Nq + n))*Dq,
                                        sxx, g_see[b*Nq + n]);
                unsigned long long key = make_key(-dist, n);
                if (key > bk) bk = key;
            }
        }
#pragma unroll
        for (int off = 16; off > 0; off >>= 1) {
            unsigned long long o = __shfl_xor_sync(0xffffffffu, bk, off);
            if (o > bk) bk = o;
        }
        nstar = 0xFFFFFFFFu - (unsigned)bk;
    }
    if (lane == 0) out[IND_OFF + token] = (float)nstar;

    // ---- fused gather + quantize + diff ----
    const float4* q4 = (const float4*)(g_cb + ((size_t)(b*Nq) + nstar) * Dq);
    const float4* x4 = (const float4*)(x + (size_t)token * Dq);
    float4* o4 = (float4*)(out + (size_t)token * Dq);

    float s32 = 0.f;
    double s = 0.0;
#pragma unroll
    for (int p = 0; p < 2; p++) {
        int f = lane + p*32;
        float4 q = q4[f], xv = x4[f];
        float dx = __fsub_rn(q.x, xv.x), dy = __fsub_rn(q.y, xv.y);
        float dz = __fsub_rn(q.z, xv.z), dw = __fsub_rn(q.w, xv.w);
        float4 r;
        r.x = __fmul_rn(__fadd_rn(q.x, __fadd_rn(xv.x, dx)), 0.5f);
        r.y = __fmul_rn(__fadd_rn(q.y, __fadd_rn(xv.y, dy)), 0.5f);
        r.z = __fmul_rn(__fadd_rn(q.z, __fadd_rn(xv.z, dz)), 0.5f);
        r.w = __fmul_rn(__fadd_rn(q.w, __fadd_rn(xv.w, dw)), 0.5f);
        o4[f] = r;
        s32 = fmaf(dx, dx, s32); s32 = fmaf(dy, dy, s32);
        s32 = fmaf(dz, dz, s32); s32 = fmaf(dw, dw, s32);
        if (p == 0) { s += (double)s32; s32 = 0.f; }
    }
    s += (double)s32;

#pragma unroll
    for (int off = 16; off > 0; off >>= 1) s += __shfl_down_sync(0xffffffffu, s, off);
    if (lane == 0) s_red[wid] = s;
    __syncthreads();
    if (tid == 0) {
        double t = 0.0;
        for (int i = 0; i < 8; i++) t += s_red[i];
        g_diff_partial[blockIdx.x] = t;
    }
}

// ---------------- kernel 4: deterministic final diff reduce ---------------
__global__ __launch_bounds__(256) void k_diff(float* __restrict__ out) {
    __shared__ double sr[256];
    int tid = threadIdx.x;
    double s = 0.0;
    for (int i = tid; i < SEL_BLOCKS; i += 256) s += g_diff_partial[i];
    sr[tid] = s;
    __syncthreads();
    for (int off = 128; off > 0; off >>= 1) {
        if (tid < off) sr[tid] += sr[tid + off];
        __syncthreads();
    }
    if (tid == 0) out[DIFF_OFF] = (float)(sr[0] / (double)Q_ELEMS);
}

// ---------------- launch ----------------
extern "C" void kernel_launch(void* const* d_in, const int* in_sizes, int n_in,
                              void* d_out, int out_size) {
    const float* inp = (const float*)d_in[0];   // (16,2048,256)
    const float* spk = (const float*)d_in[1];   // (3,16,256)
    const float* emb = (const float*)d_in[2];   // (512,256,256)
    float* out = (float*)d_out;                 // [quantize | diff | embed_ind]

    k_prep<<<Bq*Tq/8, 256>>>(inp);
    k_codebook<<<512, 128>>>(emb, spk);
    k_scores_mma<<<1024, 256>>>();
    k_select<<<SEL_BLOCKS, 256>>>(inp, out);
    k_diff<<<1, 256>>>(out);
}